// round 12
// baseline (speedup 1.0000x reference)
#include <cuda_runtime.h>
#include <cuda_bf16.h>
#include <math.h>

#define BSZ 2
#define SEQ 2048
#define DIM 1024
#define NH  16
#define HD  64
#define NTOK (BSZ*SEQ)            // 4096
#define NELEM ((size_t)NTOK*DIM)  // 4,194,304
#define WELEM ((size_t)DIM*DIM)   // 1,048,576

// Scratch (allocation-free rule: __device__ globals)
__device__ __nv_bfloat16 g_aqh[NELEM], g_aql[NELEM];     // split activations
__device__ __nv_bfloat16 g_akh[NELEM], g_akl[NELEM];
__device__ __nv_bfloat16 g_avh[NELEM], g_avl[NELEM];
__device__ __nv_bfloat16 g_Wh[4*WELEM], g_Wl[4*WELEM];   // split weights [k][n]
__device__ __nv_bfloat16 g_Qh[NELEM], g_Ql[NELEM];       // projected Q/K/V
__device__ __nv_bfloat16 g_Kh[NELEM], g_Kl[NELEM];
__device__ __nv_bfloat16 g_Vh[NELEM], g_Vl[NELEM];
__device__ __nv_bfloat16 g_Mh[NELEM], g_Ml[NELEM];       // merged attn out

// ---------------------------------------------------------------------------
// small PTX helpers
// ---------------------------------------------------------------------------
__device__ __forceinline__ unsigned packbf2(float hi, float lo) {
    unsigned d;
    asm("cvt.rn.bf16x2.f32 %0, %1, %2;" : "=r"(d) : "f"(hi), "f"(lo));
    return d;
}
__device__ __forceinline__ void cp_async16(unsigned smem_addr, const void* gptr) {
    asm volatile("cp.async.cg.shared.global [%0], [%1], 16;\n"
                 :: "r"(smem_addr), "l"(gptr));
}
__device__ __forceinline__ void cp_commit() {
    asm volatile("cp.async.commit_group;\n");
}
template <int N>
__device__ __forceinline__ void cp_wait() {
    asm volatile("cp.async.wait_group %0;\n" :: "n"(N));
}
__device__ __forceinline__ void ldsm_x4(unsigned* r, unsigned addr) {
    asm volatile("ldmatrix.sync.aligned.m8n8.x4.shared.b16 {%0,%1,%2,%3}, [%4];"
                 : "=r"(r[0]), "=r"(r[1]), "=r"(r[2]), "=r"(r[3]) : "r"(addr));
}
__device__ __forceinline__ void ldsm_x4_t(unsigned* r, unsigned addr) {
    asm volatile("ldmatrix.sync.aligned.m8n8.x4.trans.shared.b16 {%0,%1,%2,%3}, [%4];"
                 : "=r"(r[0]), "=r"(r[1]), "=r"(r[2]), "=r"(r[3]) : "r"(addr));
}
__device__ __forceinline__ void ldsm_x2_t(unsigned* r, unsigned addr) {
    asm volatile("ldmatrix.sync.aligned.m8n8.x2.trans.shared.b16 {%0,%1}, [%2];"
                 : "=r"(r[0]), "=r"(r[1]) : "r"(addr));
}
__device__ __forceinline__ void mma_bf16(float* c, const unsigned* a,
                                         unsigned b0, unsigned b1) {
    asm volatile(
        "mma.sync.aligned.m16n8k16.row.col.f32.bf16.bf16.f32 "
        "{%0,%1,%2,%3},{%4,%5,%6,%7},{%8,%9},{%0,%1,%2,%3};"
        : "+f"(c[0]), "+f"(c[1]), "+f"(c[2]), "+f"(c[3])
        : "r"(a[0]), "r"(a[1]), "r"(a[2]), "r"(a[3]), "r"(b0), "r"(b1));
}

// ---------------------------------------------------------------------------
// Pre-pass: fp32 -> bf16 hi/lo planes (elementwise; Q pre-scaled by 0.125)
// ---------------------------------------------------------------------------
__global__ void __launch_bounds__(256)
cvt_act(const float* __restrict__ q, const float* __restrict__ k,
        const float* __restrict__ v,
        __nv_bfloat16* qh, __nv_bfloat16* ql,
        __nv_bfloat16* kh, __nv_bfloat16* kl,
        __nv_bfloat16* vh, __nv_bfloat16* vl)
{
    const int z = blockIdx.z;
    const float* src = (z == 0) ? q : (z == 1) ? k : v;
    __nv_bfloat16* H = (z == 0) ? qh : (z == 1) ? kh : vh;
    __nv_bfloat16* L = (z == 0) ? ql : (z == 1) ? kl : vl;
    const float scale = (z == 0) ? 0.125f : 1.0f;

    size_t i2 = (size_t)blockIdx.x * blockDim.x + threadIdx.x;
    if (i2 < NELEM / 2) {
        float2 xv = ((const float2*)src)[i2];
        float x0 = xv.x * scale, x1 = xv.y * scale;
        unsigned hi = packbf2(x1, x0);
        float h0 = __uint_as_float(hi << 16);
        float h1 = __uint_as_float(hi & 0xffff0000u);
        unsigned lo = packbf2(x1 - h1, x0 - h0);
        ((unsigned*)H)[i2] = hi;
        ((unsigned*)L)[i2] = lo;
    }
}

__global__ void __launch_bounds__(256)
cvt_w(const float* __restrict__ Wq, const float* __restrict__ Wk,
      const float* __restrict__ Wv, const float* __restrict__ Wo,
      __nv_bfloat16* WH, __nv_bfloat16* WL)
{
    const int z = blockIdx.z;
    const float* src = (z == 0) ? Wq : (z == 1) ? Wk : (z == 2) ? Wv : Wo;
    size_t i2 = (size_t)blockIdx.x * blockDim.x + threadIdx.x;
    if (i2 < WELEM / 2) {
        float2 xv = ((const float2*)src)[i2];
        unsigned hi = packbf2(xv.y, xv.x);
        float h0 = __uint_as_float(hi << 16);
        float h1 = __uint_as_float(hi & 0xffff0000u);
        unsigned lo = packbf2(xv.y - h1, xv.x - h0);
        ((unsigned*)(WH + (size_t)z * WELEM))[i2] = hi;
        ((unsigned*)(WL + (size_t)z * WELEM))[i2] = lo;
    }
}

// ---------------------------------------------------------------------------
// bf16 3-term GEMM (fp32-accurate): C = A @ B, A[m][k] hi/lo planes,
// B[k][n] hi/lo planes. 64x128 CTA tile, 128 threads (4 warps, 32x64 warp
// tile), GBK=32, 2-stage cp.async, 4 CTAs/SM. ldmatrix operand loads:
// A via ldsm_x4 (flash-Q pattern), B via ldsm_x2_t (flash-V pattern).
// ---------------------------------------------------------------------------
#define GBM 64
#define GBN 128
#define GBK 32
#define ARS 40                       // A row stride (bf16): 80B = 5x16B, odd
#define BRS 136                      // B row stride (bf16): 272B = 17x16B, odd
// stage layout (bf16 units): AH | AL | BH | BL
#define OAH 0
#define OAL (64*ARS)                 // 2560
#define OBH (2*64*ARS)               // 5120
#define OBL (2*64*ARS + 32*BRS)      // 9472
#define STAGE_BF (2*64*ARS + 2*32*BRS)   // 13824 bf16 = 27648 B
#define GEMM_SMEM (2*STAGE_BF*2)         // 55296 B

__device__ __forceinline__ void gemm_core(
    const __nv_bfloat16* __restrict__ Ah, const __nv_bfloat16* __restrict__ Al,
    const __nv_bfloat16* __restrict__ Bh, const __nv_bfloat16* __restrict__ Bl,
    float* __restrict__ Cf,
    __nv_bfloat16* __restrict__ Ch, __nv_bfloat16* __restrict__ Cl,
    int M, int N, int K, __nv_bfloat16* sm)
{
    const int tid  = threadIdx.x;
    const int lane = tid & 31;
    const int warp = tid >> 5;           // 0..3
    const int wm   = warp >> 1;          // 0..1 (32 rows)
    const int wn   = warp & 1;           // 0..1 (64 cols)

    const int mBase = blockIdx.y * GBM;
    const int nBase = blockIdx.x * GBN;

    unsigned sbase;
    asm("{ .reg .u64 t; cvta.to.shared.u64 t, %1; cvt.u32.u64 %0, t; }"
        : "=r"(sbase) : "l"(sm));

    float c[2][8][4];
    #pragma unroll
    for (int mt = 0; mt < 2; mt++)
        #pragma unroll
        for (int nt = 0; nt < 8; nt++)
            #pragma unroll
            for (int e = 0; e < 4; e++) c[mt][nt][e] = 0.0f;

    const int niter = K / GBK;           // 32

    auto load_stage = [&](int iter, int buf) {
        const int k0 = iter * GBK;
        unsigned st = sbase + (unsigned)(buf * STAGE_BF) * 2u;
        // A planes: 64 rows x 32 bf16 = 4 x 16B chunks/row; 256 chunks/plane
        #pragma unroll
        for (int it = 0; it < 2; it++) {
            int idx = tid + 128 * it;    // 0..255
            int r = idx >> 2, cc = idx & 3;
            unsigned d = st + (unsigned)(r * ARS + cc * 8) * 2u;
            size_t src = (size_t)(mBase + r) * K + k0 + cc * 8;
            cp_async16(d + OAH * 2, Ah + src);
            cp_async16(d + OAL * 2, Al + src);
        }
        // B planes: 32 rows x 128 bf16 = 16 x 16B chunks/row; 512 chunks/plane
        #pragma unroll
        for (int it = 0; it < 4; it++) {
            int idx = tid + 128 * it;    // 0..511
            int r = idx >> 4, cc = idx & 15;
            unsigned d = st + (unsigned)(r * BRS + cc * 8) * 2u;
            size_t src = (size_t)(k0 + r) * N + nBase + cc * 8;
            cp_async16(d + OBH * 2, Bh + src);
            cp_async16(d + OBL * 2, Bl + src);
        }
    };

    load_stage(0, 0); cp_commit();
    load_stage(1, 1); cp_commit();

    for (int i = 0; i < niter; i++) {
        cp_wait<1>();
        __syncthreads();

        const unsigned st = sbase + (unsigned)((i & 1) * STAGE_BF) * 2u;

        #pragma unroll
        for (int ks = 0; ks < 2; ks++) {          // two k16 steps per k32
            // A frags (flash-Q ldsm pattern): row = wm*32 + mt*16 + (lane&15)
            unsigned ah[2][4], al[2][4];
            {
                int rsel = (lane & 15);
                int coct = (lane >> 4) << 3;      // 0 or 8 bf16
                #pragma unroll
                for (int mt = 0; mt < 2; mt++) {
                    int row = wm * 32 + mt * 16 + rsel;
                    unsigned a = st + (unsigned)(row * ARS + ks * 16 + coct) * 2u;
                    ldsm_x4(ah[mt], a + OAH * 2);
                    ldsm_x4(al[mt], a + OAL * 2);
                }
            }
            // B frags per nt (flash-V trans pattern): rows ks*16 + (lane&15)
            int brow = ks * 16 + (lane & 15);
            #pragma unroll
            for (int nt = 0; nt < 8; nt++) {
                int col = wn * 64 + nt * 8;
                unsigned a = st + (unsigned)(brow * BRS + col) * 2u;
                unsigned bh[2], bl[2];
                ldsm_x2_t(bh, a + OBH * 2);
                ldsm_x2_t(bl, a + OBL * 2);
                #pragma unroll
                for (int mt = 0; mt < 2; mt++) {
                    mma_bf16(c[mt][nt], ah[mt], bh[0], bh[1]);  // hi*hi
                    mma_bf16(c[mt][nt], ah[mt], bl[0], bl[1]);  // hi*lo
                    mma_bf16(c[mt][nt], al[mt], bh[0], bh[1]);  // lo*hi
                }
            }
        }
        __syncthreads();
        if (i + 2 < niter) load_stage(i + 2, i & 1);
        cp_commit();
    }

    // Epilogue (same c-frag mapping as R8)
    const int g  = lane >> 2;
    const int tg = lane & 3;
    if (Ch) {
        #pragma unroll
        for (int mt = 0; mt < 2; mt++) {
            int r0 = mBase + wm * 32 + mt * 16 + g;
            #pragma unroll
            for (int nt = 0; nt < 8; nt++) {
                int col = nBase + wn * 64 + nt * 8 + 2 * tg;
                #pragma unroll
                for (int half = 0; half < 2; half++) {
                    size_t off = (size_t)(r0 + 8 * half) * N + col;
                    float y0 = c[mt][nt][2 * half + 0];
                    float y1 = c[mt][nt][2 * half + 1];
                    unsigned hi = packbf2(y1, y0);
                    float h0 = __uint_as_float(hi << 16);
                    float h1 = __uint_as_float(hi & 0xffff0000u);
                    unsigned lo = packbf2(y1 - h1, y0 - h0);
                    *(unsigned*)(Ch + off) = hi;
                    *(unsigned*)(Cl + off) = lo;
                }
            }
        }
    } else {
        #pragma unroll
        for (int mt = 0; mt < 2; mt++) {
            int r0 = mBase + wm * 32 + mt * 16 + g;
            #pragma unroll
            for (int nt = 0; nt < 8; nt++) {
                int col = nBase + wn * 64 + nt * 8 + 2 * tg;
                *(float2*)(Cf + (size_t)r0 * N + col) =
                    make_float2(c[mt][nt][0], c[mt][nt][1]);
                *(float2*)(Cf + (size_t)(r0 + 8) * N + col) =
                    make_float2(c[mt][nt][2], c[mt][nt][3]);
            }
        }
    }
}

// Fused Q/K/V projections: grid.z selects the GEMM.
__global__ void __launch_bounds__(128, 4)
qkv_gemm(const __nv_bfloat16* aqh, const __nv_bfloat16* aql,
         const __nv_bfloat16* akh, const __nv_bfloat16* akl,
         const __nv_bfloat16* avh, const __nv_bfloat16* avl,
         const __nv_bfloat16* Wh, const __nv_bfloat16* Wl,
         __nv_bfloat16* Qh, __nv_bfloat16* Ql,
         __nv_bfloat16* Kh, __nv_bfloat16* Kl,
         __nv_bfloat16* Vh, __nv_bfloat16* Vl)
{
    extern __shared__ __nv_bfloat16 smb[];
    const int z = blockIdx.z;
    const __nv_bfloat16* Ah = (z == 0) ? aqh : (z == 1) ? akh : avh;
    const __nv_bfloat16* Al = (z == 0) ? aql : (z == 1) ? akl : avl;
    __nv_bfloat16* Ch = (z == 0) ? Qh : (z == 1) ? Kh : Vh;
    __nv_bfloat16* Cl = (z == 0) ? Ql : (z == 1) ? Kl : Vl;
    gemm_core(Ah, Al, Wh + (size_t)z * WELEM, Wl + (size_t)z * WELEM,
              nullptr, Ch, Cl, NTOK, DIM, DIM, smb);
}

__global__ void __launch_bounds__(128, 4)
wo_gemm(const __nv_bfloat16* Mh, const __nv_bfloat16* Ml,
        const __nv_bfloat16* Wh, const __nv_bfloat16* Wl, float* C)
{
    extern __shared__ __nv_bfloat16 smb[];
    gemm_core(Mh, Ml, Wh + 3 * WELEM, Wl + 3 * WELEM,
              C, nullptr, nullptr, NTOK, DIM, DIM, smb);
}

// ---------------------------------------------------------------------------
// Flash attention (frozen R8 mainloop): bf16 tensor cores, 3-term hi/lo,
// 128-thread CTAs over 64 q-rows, 2 CTAs/SM, gmem-direct Q frags, 2-stage
// cp.async KV. Epilogue emits merged as bf16 hi/lo planes (for wo_gemm).
// ---------------------------------------------------------------------------
#define RS 72
#define KVSTAGE (4*64*RS)
#define SB_TOTAL (2*KVSTAGE)           // 73728 B
#define OKH 0
#define OKL (64*RS)
#define OVH (128*RS)
#define OVL (192*RS)

__global__ void __launch_bounds__(128, 2)
flash_bf16(const __nv_bfloat16* __restrict__ Qh, const __nv_bfloat16* __restrict__ Ql,
           const __nv_bfloat16* __restrict__ Kh, const __nv_bfloat16* __restrict__ Kl,
           const __nv_bfloat16* __restrict__ Vh, const __nv_bfloat16* __restrict__ Vl,
           __nv_bfloat16* __restrict__ Mh, __nv_bfloat16* __restrict__ Ml,
           float* __restrict__ attn_out,
           int write_attn, const int* __restrict__ maskedp)
{
    extern __shared__ __nv_bfloat16 sb[];
    const int qt  = gridDim.x - 1 - blockIdx.x;
    const int h   = blockIdx.y;
    const int b   = blockIdx.z;
    const int tid = threadIdx.x;
    const int lane = tid & 31;
    const int w   = tid >> 5;
    const int q0  = qt * 64;
    const int masked = maskedp[0];

    unsigned sbase;
    asm("{ .reg .u64 t; cvta.to.shared.u64 t, %1; cvt.u32.u64 %0, t; }"
        : "=r"(sbase) : "l"(sb));

    const int ktmax = masked ? qt : (SEQ / 64 - 1);

    auto stage_off = [](int kt) -> unsigned { return (kt & 1) ? (unsigned)KVSTAGE : 0u; };

    auto prefetch = [&](int t) {
        if (t <= ktmax) {
            unsigned so = stage_off(t);
            int r  = tid >> 3;
            int c8 = (tid & 7) << 3;
            #pragma unroll
            for (int quarter = 0; quarter < 4; quarter++) {
                int rr = r + 16 * quarter;
                size_t gidx = ((size_t)(b * SEQ + t * 64 + rr) * DIM) + h * HD + c8;
                unsigned sa = sbase + (so + rr * RS + c8) * 2;
                cp_async16(sa + OKH * 2, Kh + gidx);
                cp_async16(sa + OKL * 2, Kl + gidx);
                cp_async16(sa + OVH * 2, Vh + gidx);
                cp_async16(sa + OVL * 2, Vl + gidx);
            }
        }
        cp_commit();
    };

    prefetch(0);
    prefetch(1);

    unsigned qf[2][4][4];
    {
        const int g  = lane >> 2;
        const int tg = lane & 3;
        const int row0 = q0 + 16 * w + g;
        size_t base0 = ((size_t)(b * SEQ + row0)     * DIM) + h * HD;
        size_t base1 = ((size_t)(b * SEQ + row0 + 8) * DIM) + h * HD;
        #pragma unroll
        for (int d = 0; d < 4; d++) {
            int c0 = 16 * d + 2 * tg;
            qf[0][d][0] = *(const unsigned*)(Qh + base0 + c0);
            qf[0][d][1] = *(const unsigned*)(Qh + base1 + c0);
            qf[0][d][2] = *(const unsigned*)(Qh + base0 + c0 + 8);
            qf[0][d][3] = *(const unsigned*)(Qh + base1 + c0 + 8);
            qf[1][d][0] = *(const unsigned*)(Ql + base0 + c0);
            qf[1][d][1] = *(const unsigned*)(Ql + base1 + c0);
            qf[1][d][2] = *(const unsigned*)(Ql + base0 + c0 + 8);
            qf[1][d][3] = *(const unsigned*)(Ql + base1 + c0 + 8);
        }
    }

    float o[8][4];
    #pragma unroll
    for (int j = 0; j < 8; j++)
        #pragma unroll
        for (int e = 0; e < 4; e++) o[j][e] = 0.0f;
    float m0 = -1e30f, m1 = -1e30f, l0 = 0.0f, l1 = 0.0f;

    const int r_lo = q0 + 16 * w + (lane >> 2);
    const int r_hi = r_lo + 8;

    for (int kt = 0; kt <= ktmax; kt++) {
        cp_wait<1>();
        __syncthreads();

        const unsigned so = stage_off(kt);
        const int k0 = kt * 64;

        float s[8][4];
        #pragma unroll
        for (int j = 0; j < 8; j++)
            #pragma unroll
            for (int e = 0; e < 4; e++) s[j][e] = 0.0f;

        #pragma unroll
        for (int j = 0; j < 8; j++) {
            unsigned kbh[8], kbl[8];
            int krow = 8 * j + (lane & 7);
            int dct  = (lane >> 3) << 3;
            ldsm_x4(&kbh[0], sbase + (so + OKH + krow * RS + dct) * 2);
            ldsm_x4(&kbh[4], sbase + (so + OKH + krow * RS + 32 + dct) * 2);
            ldsm_x4(&kbl[0], sbase + (so + OKL + krow * RS + dct) * 2);
            ldsm_x4(&kbl[4], sbase + (so + OKL + krow * RS + 32 + dct) * 2);
            #pragma unroll
            for (int d = 0; d < 4; d++) {
                mma_bf16(s[j], qf[0][d], kbh[2*d], kbh[2*d+1]);
                mma_bf16(s[j], qf[0][d], kbl[2*d], kbl[2*d+1]);
                mma_bf16(s[j], qf[1][d], kbh[2*d], kbh[2*d+1]);
            }
        }

        if (masked && kt == qt) {
            #pragma unroll
            for (int j = 0; j < 8; j++) {
                int cc = k0 + 8 * j + 2 * (lane & 3);
                if (cc     > r_lo) s[j][0] = -1e30f;
                if (cc + 1 > r_lo) s[j][1] = -1e30f;
                if (cc     > r_hi) s[j][2] = -1e30f;
                if (cc + 1 > r_hi) s[j][3] = -1e30f;
            }
        }

        float mt0 = -1e30f, mt1 = -1e30f;
        #pragma unroll
        for (int j = 0; j < 8; j++) {
            mt0 = fmaxf(mt0, fmaxf(s[j][0], s[j][1]));
            mt1 = fmaxf(mt1, fmaxf(s[j][2], s[j][3]));
        }
        mt0 = fmaxf(mt0, __shfl_xor_sync(0xffffffffu, mt0, 1));
        mt0 = fmaxf(mt0, __shfl_xor_sync(0xffffffffu, mt0, 2));
        mt1 = fmaxf(mt1, __shfl_xor_sync(0xffffffffu, mt1, 1));
        mt1 = fmaxf(mt1, __shfl_xor_sync(0xffffffffu, mt1, 2));
        float mn0 = fmaxf(m0, mt0), mn1 = fmaxf(m1, mt1);
        float a0 = __expf(m0 - mn0), a1 = __expf(m1 - mn1);
        m0 = mn0; m1 = mn1;

        float rs0 = 0.0f, rs1 = 0.0f;
        unsigned pah[4][4], pal[4][4];
        #pragma unroll
        for (int j = 0; j < 8; j++) {
            float p0 = __expf(s[j][0] - mn0);
            float p1 = __expf(s[j][1] - mn0);
            float p2 = __expf(s[j][2] - mn1);
            float p3 = __expf(s[j][3] - mn1);
            rs0 += p0 + p1; rs1 += p2 + p3;
            unsigned h01 = packbf2(p1, p0);
            unsigned h23 = packbf2(p3, p2);
            float q0f = __uint_as_float(h01 << 16);
            float q1f = __uint_as_float(h01 & 0xffff0000u);
            float q2f = __uint_as_float(h23 << 16);
            float q3f = __uint_as_float(h23 & 0xffff0000u);
            unsigned lo01 = packbf2(p1 - q1f, p0 - q0f);
            unsigned lo23 = packbf2(p3 - q3f, p2 - q2f);
            int t = j >> 1, half = j & 1;
            pah[t][2 * half + 0] = h01;
            pah[t][2 * half + 1] = h23;
            pal[t][2 * half + 0] = lo01;
            pal[t][2 * half + 1] = lo23;
        }
        rs0 += __shfl_xor_sync(0xffffffffu, rs0, 1);
        rs0 += __shfl_xor_sync(0xffffffffu, rs0, 2);
        rs1 += __shfl_xor_sync(0xffffffffu, rs1, 1);
        rs1 += __shfl_xor_sync(0xffffffffu, rs1, 2);
        l0 = l0 * a0 + rs0;
        l1 = l1 * a1 + rs1;
        #pragma unroll
        for (int j = 0; j < 8; j++) {
            o[j][0] *= a0; o[j][1] *= a0;
            o[j][2] *= a1; o[j][3] *= a1;
        }

        #pragma unroll
        for (int jn = 0; jn < 8; jn++) {
            unsigned vbh[8], vbl[8];
            ldsm_x4_t(&vbh[0], sbase + (so + OVH + lane * RS + 8 * jn) * 2);
            ldsm_x4_t(&vbh[4], sbase + (so + OVH + (32 + lane) * RS + 8 * jn) * 2);
            ldsm_x4_t(&vbl[0], sbase + (so + OVL + lane * RS + 8 * jn) * 2);
            ldsm_x4_t(&vbl[4], sbase + (so + OVL + (32 + lane) * RS + 8 * jn) * 2);
            #pragma unroll
            for (int t = 0; t < 4; t++) {
                mma_bf16(o[jn], pah[t], vbh[2*t], vbh[2*t+1]);
                mma_bf16(o[jn], pah[t], vbl[2*t], vbl[2*t+1]);
                mma_bf16(o[jn], pal[t], vbh[2*t], vbh[2*t+1]);
            }
        }

        __syncthreads();
        prefetch(kt + 2);
    }

    float il0 = 1.0f / l0, il1 = 1.0f / l1;
    #pragma unroll
    for (int jn = 0; jn < 8; jn++) {
        int col = 8 * jn + 2 * (lane & 3);
        float f00 = o[jn][0] * il0, f01 = o[jn][1] * il0;
        float f10 = o[jn][2] * il1, f11 = o[jn][3] * il1;

        size_t idx0 = ((size_t)(b * SEQ + r_lo) * DIM) + h * HD + col;
        size_t idx1 = ((size_t)(b * SEQ + r_hi) * DIM) + h * HD + col;

        unsigned hi0 = packbf2(f01, f00);
        float h00 = __uint_as_float(hi0 << 16);
        float h01v = __uint_as_float(hi0 & 0xffff0000u);
        unsigned lo0 = packbf2(f01 - h01v, f00 - h00);
        *(unsigned*)(Mh + idx0) = hi0;
        *(unsigned*)(Ml + idx0) = lo0;

        unsigned hi1 = packbf2(f11, f10);
        float h10 = __uint_as_float(hi1 << 16);
        float h11v = __uint_as_float(hi1 & 0xffff0000u);
        unsigned lo1 = packbf2(f11 - h11v, f10 - h10);
        *(unsigned*)(Mh + idx1) = hi1;
        *(unsigned*)(Ml + idx1) = lo1;

        if (write_attn) {
            *(float2*)(attn_out + (((size_t)(b * NH + h) * SEQ + r_lo) * HD) + col) =
                make_float2(f00, f01);
            *(float2*)(attn_out + (((size_t)(b * NH + h) * SEQ + r_hi) * HD) + col) =
                make_float2(f10, f11);
        }
    }
}

// ---------------------------------------------------------------------------
extern "C" void kernel_launch(void* const* d_in, const int* in_sizes, int n_in,
                              void* d_out, int out_size)
{
    const float* q  = (const float*)d_in[0];
    const float* k  = (const float*)d_in[1];
    const float* v  = (const float*)d_in[2];
    const float* Wq = (const float*)d_in[3];
    const float* Wk = (const float*)d_in[4];
    const float* Wv = (const float*)d_in[5];
    const float* Wo = (const float*)d_in[6];
    const int* masked = (const int*)d_in[7];
    float* out = (float*)d_out;

    __nv_bfloat16 *paqh, *paql, *pakh, *pakl, *pavh, *pavl, *pWh, *pWl;
    __nv_bfloat16 *pQh, *pQl, *pKh, *pKl, *pVh, *pVl, *pMh, *pMl;
    cudaGetSymbolAddress((void**)&paqh, g_aqh);
    cudaGetSymbolAddress((void**)&paql, g_aql);
    cudaGetSymbolAddress((void**)&pakh, g_akh);
    cudaGetSymbolAddress((void**)&pakl, g_akl);
    cudaGetSymbolAddress((void**)&pavh, g_avh);
    cudaGetSymbolAddress((void**)&pavl, g_avl);
    cudaGetSymbolAddress((void**)&pWh, g_Wh);
    cudaGetSymbolAddress((void**)&pWl, g_Wl);
    cudaGetSymbolAddress((void**)&pQh, g_Qh);
    cudaGetSymbolAddress((void**)&pQl, g_Ql);
    cudaGetSymbolAddress((void**)&pKh, g_Kh);
    cudaGetSymbolAddress((void**)&pKl, g_Kl);
    cudaGetSymbolAddress((void**)&pVh, g_Vh);
    cudaGetSymbolAddress((void**)&pVl, g_Vl);
    cudaGetSymbolAddress((void**)&pMh, g_Mh);
    cudaGetSymbolAddress((void**)&pMl, g_Ml);

    cudaFuncSetAttribute(qkv_gemm, cudaFuncAttributeMaxDynamicSharedMemorySize,
                         GEMM_SMEM);
    cudaFuncSetAttribute(wo_gemm, cudaFuncAttributeMaxDynamicSharedMemorySize,
                         GEMM_SMEM);

    // Pre-pass: split activations and weights into bf16 hi/lo planes
    dim3 gCvtA((unsigned)((NELEM / 2 + 255) / 256), 1, 3);
    cvt_act<<<gCvtA, 256>>>(q, k, v, paqh, paql, pakh, pakl, pavh, pavl);
    dim3 gCvtW((unsigned)((WELEM / 2 + 255) / 256), 1, 4);
    cvt_w<<<gCvtW, 256>>>(Wq, Wk, Wv, Wo, pWh, pWl);

    // Fused Q/K/V projections (bf16 3-term, fp32-accurate)
    dim3 gQKV(DIM / GBN, NTOK / GBM, 3);   // (8, 64, 3)
    qkv_gemm<<<gQKV, 128, GEMM_SMEM>>>(paqh, paql, pakh, pakl, pavh, pavl,
                                       pWh, pWl,
                                       pQh, pQl, pKh, pKl, pVh, pVl);

    // Attention (frozen R8 mainloop; epilogue emits Mh/Ml)
    int write_attn = (out_size >= (int)(2 * NELEM)) ? 1 : 0;
    float* attn_ptr = out + NELEM;
    size_t fl_smem = (size_t)SB_TOTAL * sizeof(__nv_bfloat16);
    cudaFuncSetAttribute(flash_bf16, cudaFuncAttributeMaxDynamicSharedMemorySize,
                         (int)fl_smem);
    dim3 gAttn(SEQ / 64, NH, BSZ);         // (32, 16, 2)
    flash_bf16<<<gAttn, 128, fl_smem>>>(pQh, pQl, pKh, pKl, pVh, pVl,
                                        pMh, pMl, attn_ptr, write_attn, masked);

    // Output projection (bf16 3-term, fp32 out)
    dim3 gWo(DIM / GBN, NTOK / GBM);       // (8, 64)
    wo_gemm<<<gWo, 128, GEMM_SMEM>>>(pMh, pMl, pWh, pWl, out);
}

// round 13
// speedup vs baseline: 1.1618x; 1.1618x over previous
#include <cuda_runtime.h>
#include <cuda_bf16.h>
#include <math.h>

#define BSZ 2
#define SEQ 2048
#define DIM 1024
#define NH  16
#define HD  64
#define NTOK (BSZ*SEQ)            // 4096
#define NELEM ((size_t)NTOK*DIM)  // 4,194,304

// Scratch (allocation-free rule: __device__ globals)
__device__ float g_M[NELEM];               // merged attention output [B,S,H*HD]
__device__ __nv_bfloat16 g_Qh[NELEM], g_Ql[NELEM];
__device__ __nv_bfloat16 g_Kh[NELEM], g_Kl[NELEM];
__device__ __nv_bfloat16 g_Vh[NELEM], g_Vl[NELEM];

// ---------------------------------------------------------------------------
// small PTX helpers
// ---------------------------------------------------------------------------
__device__ __forceinline__ unsigned f2tf32(float f) {
    unsigned r;
    asm("cvt.rna.tf32.f32 %0, %1;" : "=r"(r) : "f"(f));
    return r;
}
__device__ __forceinline__ unsigned packbf2(float hi, float lo) {
    unsigned d;
    asm("cvt.rn.bf16x2.f32 %0, %1, %2;" : "=r"(d) : "f"(hi), "f"(lo));
    return d;
}
__device__ __forceinline__ void cp_async16(unsigned smem_addr, const void* gptr) {
    asm volatile("cp.async.cg.shared.global [%0], [%1], 16;\n"
                 :: "r"(smem_addr), "l"(gptr));
}
__device__ __forceinline__ void cp_commit() {
    asm volatile("cp.async.commit_group;\n");
}
template <int N>
__device__ __forceinline__ void cp_wait() {
    asm volatile("cp.async.wait_group %0;\n" :: "n"(N));
}
__device__ __forceinline__ void ldsm_x4(unsigned* r, unsigned addr) {
    asm volatile("ldmatrix.sync.aligned.m8n8.x4.shared.b16 {%0,%1,%2,%3}, [%4];"
                 : "=r"(r[0]), "=r"(r[1]), "=r"(r[2]), "=r"(r[3]) : "r"(addr));
}
__device__ __forceinline__ void ldsm_x4_t(unsigned* r, unsigned addr) {
    asm volatile("ldmatrix.sync.aligned.m8n8.x4.trans.shared.b16 {%0,%1,%2,%3}, [%4];"
                 : "=r"(r[0]), "=r"(r[1]), "=r"(r[2]), "=r"(r[3]) : "r"(addr));
}
__device__ __forceinline__ void mma_bf16(float* c, const unsigned* a,
                                         unsigned b0, unsigned b1) {
    asm volatile(
        "mma.sync.aligned.m16n8k16.row.col.f32.bf16.bf16.f32 "
        "{%0,%1,%2,%3},{%4,%5,%6,%7},{%8,%9},{%0,%1,%2,%3};"
        : "+f"(c[0]), "+f"(c[1]), "+f"(c[2]), "+f"(c[3])
        : "r"(a[0]), "r"(a[1]), "r"(a[2]), "r"(a[3]), "r"(b0), "r"(b1));
}

// ---------------------------------------------------------------------------
// TF32 GEMM core (exact R8): 64x128 CTA tile, 128 threads (4 warps,
// 32x64 warp tile), GBK=32, 2-stage cp.async pipeline, 4 CTAs/SM.
// ---------------------------------------------------------------------------
#define GBM 64
#define GBN 128
#define GBK 32
#define ASTRIDE 36
#define BSTRIDE 136
#define STAGE_FLOATS (GBM*ASTRIDE + GBK*BSTRIDE)   // 6656
#define GEMM_SMEM (2*STAGE_FLOATS*4)               // 53248 B

__device__ __forceinline__ void gemm_core(
    const float* __restrict__ A, const float* __restrict__ B,
    float* __restrict__ Cf,
    __nv_bfloat16* __restrict__ Ch, __nv_bfloat16* __restrict__ Cl,
    float scale, int M, int N, int K, float* sm)
{
    const int tid  = threadIdx.x;
    const int lane = tid & 31;
    const int warp = tid >> 5;
    const int wm   = warp >> 1;
    const int wn   = warp & 1;

    const int bRow = blockIdx.y;
    const int bCol = blockIdx.x;

    const float* Ab = A + (size_t)bRow * GBM * K;
    const float* Bb = B + (size_t)bCol * GBN;

    unsigned smem_base;
    asm("{ .reg .u64 t; cvta.to.shared.u64 t, %1; cvt.u32.u64 %0, t; }"
        : "=r"(smem_base) : "l"(sm));

    float c[2][8][4];
    #pragma unroll
    for (int mt = 0; mt < 2; mt++)
        #pragma unroll
        for (int nt = 0; nt < 8; nt++)
            #pragma unroll
            for (int e = 0; e < 4; e++) c[mt][nt][e] = 0.0f;

    const int niter = K / GBK;

    auto load_stage = [&](int iter, int buf) {
        const int k0 = iter * GBK;
        unsigned aBase = smem_base + (unsigned)(buf * STAGE_FLOATS) * 4u;
        unsigned bBase = aBase + GBM * ASTRIDE * 4u;
        #pragma unroll
        for (int it = 0; it < 4; it++) {
            int r  = (tid >> 3) + 16 * it;
            int c4 = (tid & 7) * 4;
            cp_async16(aBase + (r * ASTRIDE + c4) * 4u,
                       Ab + (size_t)r * K + k0 + c4);
        }
        #pragma unroll
        for (int it = 0; it < 8; it++) {
            int idx = tid + 128 * it;
            int r   = idx >> 5;
            int c4  = (idx & 31) * 4;
            cp_async16(bBase + (r * BSTRIDE + c4) * 4u,
                       Bb + (size_t)(k0 + r) * N + c4);
        }
    };

    load_stage(0, 0); cp_commit();
    load_stage(1, 1); cp_commit();

    const int g  = lane >> 2;
    const int tg = lane & 3;

    for (int i = 0; i < niter; i++) {
        cp_wait<1>();
        __syncthreads();

        const int buf = i & 1;
        const float* As = sm + buf * STAGE_FLOATS;
        const float* Bs = As + GBM * ASTRIDE;

        #pragma unroll
        for (int kk = 0; kk < GBK / 8; kk++) {
            unsigned af[2][4], bf[8][2];
            const int c0 = kk * 8 + tg;
            #pragma unroll
            for (int mt = 0; mt < 2; mt++) {
                int r0 = wm * 32 + mt * 16 + g;
                af[mt][0] = f2tf32(As[r0       * ASTRIDE + c0]);
                af[mt][1] = f2tf32(As[(r0 + 8) * ASTRIDE + c0]);
                af[mt][2] = f2tf32(As[r0       * ASTRIDE + c0 + 4]);
                af[mt][3] = f2tf32(As[(r0 + 8) * ASTRIDE + c0 + 4]);
            }
            #pragma unroll
            for (int nt = 0; nt < 8; nt++) {
                int col = wn * 64 + nt * 8 + g;
                bf[nt][0] = f2tf32(Bs[c0       * BSTRIDE + col]);
                bf[nt][1] = f2tf32(Bs[(c0 + 4) * BSTRIDE + col]);
            }
            #pragma unroll
            for (int mt = 0; mt < 2; mt++)
                #pragma unroll
                for (int nt = 0; nt < 8; nt++) {
                    asm volatile(
                        "mma.sync.aligned.m16n8k8.row.col.f32.tf32.tf32.f32 "
                        "{%0,%1,%2,%3},{%4,%5,%6,%7},{%8,%9},{%0,%1,%2,%3};\n"
                        : "+f"(c[mt][nt][0]), "+f"(c[mt][nt][1]),
                          "+f"(c[mt][nt][2]), "+f"(c[mt][nt][3])
                        : "r"(af[mt][0]), "r"(af[mt][1]),
                          "r"(af[mt][2]), "r"(af[mt][3]),
                          "r"(bf[nt][0]), "r"(bf[nt][1]));
                }
        }
        __syncthreads();
        if (i + 2 < niter) load_stage(i + 2, buf);
        cp_commit();
    }

    // Epilogue
    if (Ch) {
        #pragma unroll
        for (int mt = 0; mt < 2; mt++) {
            int r0 = bRow * GBM + wm * 32 + mt * 16 + g;
            #pragma unroll
            for (int nt = 0; nt < 8; nt++) {
                int col = bCol * GBN + wn * 64 + nt * 8 + 2 * tg;
                #pragma unroll
                for (int half = 0; half < 2; half++) {
                    size_t off = (size_t)(r0 + 8 * half) * N + col;
                    float y0 = c[mt][nt][2 * half + 0] * scale;
                    float y1 = c[mt][nt][2 * half + 1] * scale;
                    unsigned hi = packbf2(y1, y0);
                    float h0 = __uint_as_float(hi << 16);
                    float h1 = __uint_as_float(hi & 0xffff0000u);
                    unsigned lo = packbf2(y1 - h1, y0 - h0);
                    *(unsigned*)(Ch + off) = hi;
                    *(unsigned*)(Cl + off) = lo;
                }
            }
        }
    } else {
        float* Cb = Cf + (size_t)bRow * GBM * N + bCol * GBN;
        #pragma unroll
        for (int mt = 0; mt < 2; mt++) {
            int r0 = wm * 32 + mt * 16 + g;
            #pragma unroll
            for (int nt = 0; nt < 8; nt++) {
                int col = wn * 64 + nt * 8 + 2 * tg;
                *(float2*)(Cb + (size_t)r0 * N + col) =
                    make_float2(c[mt][nt][0], c[mt][nt][1]);
                *(float2*)(Cb + (size_t)(r0 + 8) * N + col) =
                    make_float2(c[mt][nt][2], c[mt][nt][3]);
            }
        }
    }
}

// Fused Q/K/V projections: grid.z selects the GEMM.
__global__ void __launch_bounds__(128, 4)
qkv_gemm(const float* __restrict__ q, const float* __restrict__ k,
         const float* __restrict__ v,
         const float* __restrict__ Wq, const float* __restrict__ Wk,
         const float* __restrict__ Wv,
         __nv_bfloat16* Qh, __nv_bfloat16* Ql,
         __nv_bfloat16* Kh, __nv_bfloat16* Kl,
         __nv_bfloat16* Vh, __nv_bfloat16* Vl)
{
    extern __shared__ float sm[];
    const int z = blockIdx.z;
    const float* A = (z == 0) ? q  : (z == 1) ? k  : v;
    const float* B = (z == 0) ? Wq : (z == 1) ? Wk : Wv;
    __nv_bfloat16* Ch = (z == 0) ? Qh : (z == 1) ? Kh : Vh;
    __nv_bfloat16* Cl = (z == 0) ? Ql : (z == 1) ? Kl : Vl;
    float scale = (z == 0) ? 0.125f : 1.0f;
    gemm_core(A, B, nullptr, Ch, Cl, scale, NTOK, DIM, DIM, sm);
}

__global__ void __launch_bounds__(128, 4)
wo_gemm(const float* __restrict__ A, const float* __restrict__ B,
        float* __restrict__ C)
{
    extern __shared__ float sm[];
    gemm_core(A, B, C, nullptr, nullptr, 1.0f, NTOK, DIM, DIM, sm);
}

// ---------------------------------------------------------------------------
// Flash attention: R8 mainloop upgraded to a 3-stage KV pipeline with a
// SINGLE __syncthreads per k-tile and prefetch issued BEFORE compute.
// 128-thread CTAs over 64 q-rows, 2 CTAs/SM (smem 110.6KB), gmem-direct
// Q frags, padded (conflict-free) smem layout.
// ---------------------------------------------------------------------------
#define RS 72
#define KVSTAGE (4*64*RS)              // 18432 bf16 per stage
#define SB_TOTAL (3*KVSTAGE)           // 55296 bf16 = 110592 B
#define OKH 0
#define OKL (64*RS)
#define OVH (128*RS)
#define OVL (192*RS)

__global__ void __launch_bounds__(128, 2)
flash_bf16(const __nv_bfloat16* __restrict__ Qh, const __nv_bfloat16* __restrict__ Ql,
           const __nv_bfloat16* __restrict__ Kh, const __nv_bfloat16* __restrict__ Kl,
           const __nv_bfloat16* __restrict__ Vh, const __nv_bfloat16* __restrict__ Vl,
           float* __restrict__ merged, float* __restrict__ attn_out,
           int write_attn, const int* __restrict__ maskedp)
{
    extern __shared__ __nv_bfloat16 sb[];
    const int qt  = gridDim.x - 1 - blockIdx.x;   // heavy blocks first
    const int h   = blockIdx.y;
    const int b   = blockIdx.z;
    const int tid = threadIdx.x;
    const int lane = tid & 31;
    const int w   = tid >> 5;                     // 0..3
    const int q0  = qt * 64;
    const int masked = maskedp[0];

    unsigned sbase;
    asm("{ .reg .u64 t; cvta.to.shared.u64 t, %1; cvt.u32.u64 %0, t; }"
        : "=r"(sbase) : "l"(sb));

    const int ktmax = masked ? qt : (SEQ / 64 - 1);

    // stage s = kt % 3
    auto stage_off = [](int kt) -> unsigned {
        int s = kt % 3;
        return (unsigned)(s * KVSTAGE);
    };

    auto prefetch = [&](int t) {
        if (t <= ktmax) {
            unsigned so = stage_off(t);
            int r  = tid >> 3;
            int c8 = (tid & 7) << 3;
            #pragma unroll
            for (int quarter = 0; quarter < 4; quarter++) {
                int rr = r + 16 * quarter;
                size_t gidx = ((size_t)(b * SEQ + t * 64 + rr) * DIM) + h * HD + c8;
                unsigned sa = sbase + (so + rr * RS + c8) * 2;
                cp_async16(sa + OKH * 2, Kh + gidx);
                cp_async16(sa + OKL * 2, Kl + gidx);
                cp_async16(sa + OVH * 2, Vh + gidx);
                cp_async16(sa + OVL * 2, Vl + gidx);
            }
        }
        cp_commit();   // exactly one group per call (possibly empty)
    };

    prefetch(0);
    prefetch(1);

    // Q A-frags directly from gmem: [plane][dstep][4regs]
    unsigned qf[2][4][4];
    {
        const int g  = lane >> 2;
        const int tg = lane & 3;
        const int row0 = q0 + 16 * w + g;
        size_t base0 = ((size_t)(b * SEQ + row0)     * DIM) + h * HD;
        size_t base1 = ((size_t)(b * SEQ + row0 + 8) * DIM) + h * HD;
        #pragma unroll
        for (int d = 0; d < 4; d++) {
            int c0 = 16 * d + 2 * tg;
            qf[0][d][0] = *(const unsigned*)(Qh + base0 + c0);
            qf[0][d][1] = *(const unsigned*)(Qh + base1 + c0);
            qf[0][d][2] = *(const unsigned*)(Qh + base0 + c0 + 8);
            qf[0][d][3] = *(const unsigned*)(Qh + base1 + c0 + 8);
            qf[1][d][0] = *(const unsigned*)(Ql + base0 + c0);
            qf[1][d][1] = *(const unsigned*)(Ql + base1 + c0);
            qf[1][d][2] = *(const unsigned*)(Ql + base0 + c0 + 8);
            qf[1][d][3] = *(const unsigned*)(Ql + base1 + c0 + 8);
        }
    }

    float o[8][4];
    #pragma unroll
    for (int j = 0; j < 8; j++)
        #pragma unroll
        for (int e = 0; e < 4; e++) o[j][e] = 0.0f;
    float m0 = -1e30f, m1 = -1e30f, l0 = 0.0f, l1 = 0.0f;

    const int r_lo = q0 + 16 * w + (lane >> 2);
    const int r_hi = r_lo + 8;

    for (int kt = 0; kt <= ktmax; kt++) {
        cp_wait<1>();          // stage kt landed (stage kt+1 may be in flight)
        __syncthreads();       // single barrier: also proves all warps finished
                               // reading stage (kt-1) -> safe to refill it now
        prefetch(kt + 2);      // into stage (kt+2)%3 == (kt-1)%3, BEFORE compute

        const unsigned so = stage_off(kt);
        const int k0 = kt * 64;

        // ---- QK^T ----
        float s[8][4];
        #pragma unroll
        for (int j = 0; j < 8; j++)
            #pragma unroll
            for (int e = 0; e < 4; e++) s[j][e] = 0.0f;

        #pragma unroll
        for (int j = 0; j < 8; j++) {
            unsigned kbh[8], kbl[8];
            int krow = 8 * j + (lane & 7);
            int dct  = (lane >> 3) << 3;
            ldsm_x4(&kbh[0], sbase + (so + OKH + krow * RS + dct) * 2);
            ldsm_x4(&kbh[4], sbase + (so + OKH + krow * RS + 32 + dct) * 2);
            ldsm_x4(&kbl[0], sbase + (so + OKL + krow * RS + dct) * 2);
            ldsm_x4(&kbl[4], sbase + (so + OKL + krow * RS + 32 + dct) * 2);
            #pragma unroll
            for (int d = 0; d < 4; d++) {
                mma_bf16(s[j], qf[0][d], kbh[2*d], kbh[2*d+1]);
                mma_bf16(s[j], qf[0][d], kbl[2*d], kbl[2*d+1]);
                mma_bf16(s[j], qf[1][d], kbh[2*d], kbh[2*d+1]);
            }
        }

        // ---- causal mask (diagonal tile only) ----
        if (masked && kt == qt) {
            #pragma unroll
            for (int j = 0; j < 8; j++) {
                int cc = k0 + 8 * j + 2 * (lane & 3);
                if (cc     > r_lo) s[j][0] = -1e30f;
                if (cc + 1 > r_lo) s[j][1] = -1e30f;
                if (cc     > r_hi) s[j][2] = -1e30f;
                if (cc + 1 > r_hi) s[j][3] = -1e30f;
            }
        }

        // ---- online softmax ----
        float mt0 = -1e30f, mt1 = -1e30f;
        #pragma unroll
        for (int j = 0; j < 8; j++) {
            mt0 = fmaxf(mt0, fmaxf(s[j][0], s[j][1]));
            mt1 = fmaxf(mt1, fmaxf(s[j][2], s[j][3]));
        }
        mt0 = fmaxf(mt0, __shfl_xor_sync(0xffffffffu, mt0, 1));
        mt0 = fmaxf(mt0, __shfl_xor_sync(0xffffffffu, mt0, 2));
        mt1 = fmaxf(mt1, __shfl_xor_sync(0xffffffffu, mt1, 1));
        mt1 = fmaxf(mt1, __shfl_xor_sync(0xffffffffu, mt1, 2));
        float mn0 = fmaxf(m0, mt0), mn1 = fmaxf(m1, mt1);
        float a0 = __expf(m0 - mn0), a1 = __expf(m1 - mn1);
        m0 = mn0; m1 = mn1;

        float rs0 = 0.0f, rs1 = 0.0f;
        unsigned pah[4][4], pal[4][4];
        #pragma unroll
        for (int j = 0; j < 8; j++) {
            float p0 = __expf(s[j][0] - mn0);
            float p1 = __expf(s[j][1] - mn0);
            float p2 = __expf(s[j][2] - mn1);
            float p3 = __expf(s[j][3] - mn1);
            rs0 += p0 + p1; rs1 += p2 + p3;
            unsigned h01 = packbf2(p1, p0);
            unsigned h23 = packbf2(p3, p2);
            float q0f = __uint_as_float(h01 << 16);
            float q1f = __uint_as_float(h01 & 0xffff0000u);
            float q2f = __uint_as_float(h23 << 16);
            float q3f = __uint_as_float(h23 & 0xffff0000u);
            unsigned lo01 = packbf2(p1 - q1f, p0 - q0f);
            unsigned lo23 = packbf2(p3 - q3f, p2 - q2f);
            int t = j >> 1, half = j & 1;
            pah[t][2 * half + 0] = h01;
            pah[t][2 * half + 1] = h23;
            pal[t][2 * half + 0] = lo01;
            pal[t][2 * half + 1] = lo23;
        }
        rs0 += __shfl_xor_sync(0xffffffffu, rs0, 1);
        rs0 += __shfl_xor_sync(0xffffffffu, rs0, 2);
        rs1 += __shfl_xor_sync(0xffffffffu, rs1, 1);
        rs1 += __shfl_xor_sync(0xffffffffu, rs1, 2);
        l0 = l0 * a0 + rs0;
        l1 = l1 * a1 + rs1;
        #pragma unroll
        for (int j = 0; j < 8; j++) {
            o[j][0] *= a0; o[j][1] *= a0;
            o[j][2] *= a1; o[j][3] *= a1;
        }

        // ---- PV ----
        #pragma unroll
        for (int jn = 0; jn < 8; jn++) {
            unsigned vbh[8], vbl[8];
            ldsm_x4_t(&vbh[0], sbase + (so + OVH + lane * RS + 8 * jn) * 2);
            ldsm_x4_t(&vbh[4], sbase + (so + OVH + (32 + lane) * RS + 8 * jn) * 2);
            ldsm_x4_t(&vbl[0], sbase + (so + OVL + lane * RS + 8 * jn) * 2);
            ldsm_x4_t(&vbl[4], sbase + (so + OVL + (32 + lane) * RS + 8 * jn) * 2);
            #pragma unroll
            for (int t = 0; t < 4; t++) {
                mma_bf16(o[jn], pah[t], vbh[2*t], vbh[2*t+1]);
                mma_bf16(o[jn], pah[t], vbl[2*t], vbl[2*t+1]);
                mma_bf16(o[jn], pal[t], vbh[2*t], vbh[2*t+1]);
            }
        }
        // no trailing barrier: next iteration's single barrier covers the
        // read-before-overwrite hazard (3 stages guarantee the prefetch
        // target is never the stage being computed or the next one).
    }

    // ---- finalize + write ----
    float il0 = 1.0f / l0, il1 = 1.0f / l1;
    #pragma unroll
    for (int jn = 0; jn < 8; jn++) {
        int col = 8 * jn + 2 * (lane & 3);
        float f00 = o[jn][0] * il0, f01 = o[jn][1] * il0;
        float f10 = o[jn][2] * il1, f11 = o[jn][3] * il1;
        *(float2*)(merged + ((size_t)(b * SEQ + r_lo) * DIM) + h * HD + col) =
            make_float2(f00, f01);
        *(float2*)(merged + ((size_t)(b * SEQ + r_hi) * DIM) + h * HD + col) =
            make_float2(f10, f11);
        if (write_attn) {
            *(float2*)(attn_out + (((size_t)(b * NH + h) * SEQ + r_lo) * HD) + col) =
                make_float2(f00, f01);
            *(float2*)(attn_out + (((size_t)(b * NH + h) * SEQ + r_hi) * HD) + col) =
                make_float2(f10, f11);
        }
    }
}

// ---------------------------------------------------------------------------
extern "C" void kernel_launch(void* const* d_in, const int* in_sizes, int n_in,
                              void* d_out, int out_size)
{
    const float* q  = (const float*)d_in[0];
    const float* k  = (const float*)d_in[1];
    const float* v  = (const float*)d_in[2];
    const float* Wq = (const float*)d_in[3];
    const float* Wk = (const float*)d_in[4];
    const float* Wv = (const float*)d_in[5];
    const float* Wo = (const float*)d_in[6];
    const int* masked = (const int*)d_in[7];
    float* out = (float*)d_out;

    float* pM;
    __nv_bfloat16 *pQh, *pQl, *pKh, *pKl, *pVh, *pVl;
    cudaGetSymbolAddress((void**)&pM,  g_M);
    cudaGetSymbolAddress((void**)&pQh, g_Qh);
    cudaGetSymbolAddress((void**)&pQl, g_Ql);
    cudaGetSymbolAddress((void**)&pKh, g_Kh);
    cudaGetSymbolAddress((void**)&pKl, g_Kl);
    cudaGetSymbolAddress((void**)&pVh, g_Vh);
    cudaGetSymbolAddress((void**)&pVl, g_Vl);

    cudaFuncSetAttribute(qkv_gemm, cudaFuncAttributeMaxDynamicSharedMemorySize,
                         GEMM_SMEM);
    cudaFuncSetAttribute(wo_gemm, cudaFuncAttributeMaxDynamicSharedMemorySize,
                         GEMM_SMEM);

    // Fused Q/K/V projections (exact R8 GEMM core)
    dim3 gQKV(DIM / GBN, NTOK / GBM, 3);   // (8, 64, 3)
    qkv_gemm<<<gQKV, 128, GEMM_SMEM>>>(q, k, v, Wq, Wk, Wv,
                                       pQh, pQl, pKh, pKl, pVh, pVl);

    // Attention: 3-stage KV pipeline, single barrier per tile, 2 CTAs/SM
    int write_attn = (out_size >= (int)(2 * NELEM)) ? 1 : 0;
    float* attn_ptr = out + NELEM;
    size_t fl_smem = (size_t)SB_TOTAL * sizeof(__nv_bfloat16);   // 110592 B
    cudaFuncSetAttribute(flash_bf16, cudaFuncAttributeMaxDynamicSharedMemorySize,
                         (int)fl_smem);
    dim3 gAttn(SEQ / 64, NH, BSZ);         // (32, 16, 2)
    flash_bf16<<<gAttn, 128, fl_smem>>>(pQh, pQl, pKh, pKl, pVh, pVl,
                                        pM, attn_ptr, write_attn, masked);

    // Output projection
    dim3 gWo(DIM / GBN, NTOK / GBM);       // (8, 64)
    wo_gemm<<<gWo, 128, GEMM_SMEM>>>(pM, Wo, out);
}

// round 14
// speedup vs baseline: 1.1891x; 1.0236x over previous
#include <cuda_runtime.h>
#include <cuda_bf16.h>
#include <math.h>

#define BSZ 2
#define SEQ 2048
#define DIM 1024
#define NH  16
#define HD  64
#define NTOK (BSZ*SEQ)            // 4096
#define NELEM ((size_t)NTOK*DIM)  // 4,194,304
#define WELEM ((size_t)DIM*DIM)   // 1,048,576

// Scratch (allocation-free rule: __device__ globals)
__device__ float g_M[NELEM];               // merged attention output [B,S,H*HD]
__device__ float g_Wt[4*WELEM];            // transposed+RNA-rounded weights [n][k]
__device__ __nv_bfloat16 g_Qh[NELEM], g_Ql[NELEM];
__device__ __nv_bfloat16 g_Kh[NELEM], g_Kl[NELEM];
__device__ __nv_bfloat16 g_Vh[NELEM], g_Vl[NELEM];

// ---------------------------------------------------------------------------
// small PTX helpers
// ---------------------------------------------------------------------------
__device__ __forceinline__ unsigned f2tf32(float f) {
    unsigned r;
    asm("cvt.rna.tf32.f32 %0, %1;" : "=r"(r) : "f"(f));
    return r;
}
__device__ __forceinline__ unsigned packbf2(float hi, float lo) {
    unsigned d;
    asm("cvt.rn.bf16x2.f32 %0, %1, %2;" : "=r"(d) : "f"(hi), "f"(lo));
    return d;
}
__device__ __forceinline__ void cp_async16(unsigned smem_addr, const void* gptr) {
    asm volatile("cp.async.cg.shared.global [%0], [%1], 16;\n"
                 :: "r"(smem_addr), "l"(gptr));
}
__device__ __forceinline__ void cp_commit() {
    asm volatile("cp.async.commit_group;\n");
}
template <int N>
__device__ __forceinline__ void cp_wait() {
    asm volatile("cp.async.wait_group %0;\n" :: "n"(N));
}
__device__ __forceinline__ void ldsm_x4(unsigned* r, unsigned addr) {
    asm volatile("ldmatrix.sync.aligned.m8n8.x4.shared.b16 {%0,%1,%2,%3}, [%4];"
                 : "=r"(r[0]), "=r"(r[1]), "=r"(r[2]), "=r"(r[3]) : "r"(addr));
}
__device__ __forceinline__ void ldsm_x4_t(unsigned* r, unsigned addr) {
    asm volatile("ldmatrix.sync.aligned.m8n8.x4.trans.shared.b16 {%0,%1,%2,%3}, [%4];"
                 : "=r"(r[0]), "=r"(r[1]), "=r"(r[2]), "=r"(r[3]) : "r"(addr));
}
__device__ __forceinline__ void mma_bf16(float* c, const unsigned* a,
                                         unsigned b0, unsigned b1) {
    asm volatile(
        "mma.sync.aligned.m16n8k16.row.col.f32.bf16.bf16.f32 "
        "{%0,%1,%2,%3},{%4,%5,%6,%7},{%8,%9},{%0,%1,%2,%3};"
        : "+f"(c[0]), "+f"(c[1]), "+f"(c[2]), "+f"(c[3])
        : "r"(a[0]), "r"(a[1]), "r"(a[2]), "r"(a[3]), "r"(b0), "r"(b1));
}
__device__ __forceinline__ void mma_tf32(float* c, const unsigned* a,
                                         unsigned b0, unsigned b1) {
    asm volatile(
        "mma.sync.aligned.m16n8k8.row.col.f32.tf32.tf32.f32 "
        "{%0,%1,%2,%3},{%4,%5,%6,%7},{%8,%9},{%0,%1,%2,%3};"
        : "+f"(c[0]), "+f"(c[1]), "+f"(c[2]), "+f"(c[3])
        : "r"(a[0]), "r"(a[1]), "r"(a[2]), "r"(a[3]), "r"(b0), "r"(b1));
}

// ---------------------------------------------------------------------------
// Pre-pass: W[k][n] -> Wt[n][k], RNA-rounded to the tf32 grid (fp32 storage).
// ---------------------------------------------------------------------------
__global__ void __launch_bounds__(1024)
wtrans(const float* __restrict__ Wq, const float* __restrict__ Wk,
       const float* __restrict__ Wv, const float* __restrict__ Wo,
       float* __restrict__ Wt)
{
    __shared__ float t[32][33];
    const int z = blockIdx.z;
    const float* W = (z == 0) ? Wq : (z == 1) ? Wk : (z == 2) ? Wv : Wo;
    const int n0 = blockIdx.x * 32, k0 = blockIdx.y * 32;
    const int tx = threadIdx.x, ty = threadIdx.y;

    t[ty][tx] = W[(size_t)(k0 + ty) * DIM + n0 + tx];
    __syncthreads();
    float val = t[tx][ty];   // = W[k0+tx][n0+ty] = Wt[n0+ty][k0+tx]
    Wt[(size_t)z * WELEM + (size_t)(n0 + ty) * DIM + k0 + tx] =
        __uint_as_float(f2tf32(val));
}

// ---------------------------------------------------------------------------
// TF32 GEMM core, ldmatrix operand path:
//   C[M,N] = A[M,K] @ B,  A row-major fp32 (raw; RNA cvt on fragments),
//   B given as Bt[n][k] fp32 (pre-rounded by wtrans).
// 64x128 CTA tile, 128 threads (4 warps, 32x64 warp tile), GBK=32,
// 2-stage cp.async, 4 CTAs/SM. Inner loop: 6 LDSM.x4 + 8 CVT + 16 MMA.
// Row stride 144B = 9 x 16B chunks -> every LDSM phase is bank-conflict-free.
// ---------------------------------------------------------------------------
#define GBM 64
#define GBN 128
#define GBK 32
#define TRS 36                              // row stride in floats (144 B)
#define STAGE_FLOATS ((GBM + GBN) * TRS)    // (64+128)*36 = 6912
#define GEMM_SMEM (2*STAGE_FLOATS*4)        // 55296 B

__device__ __forceinline__ void gemm_core(
    const float* __restrict__ A, const float* __restrict__ Bt,
    float* __restrict__ Cf,
    __nv_bfloat16* __restrict__ Ch, __nv_bfloat16* __restrict__ Cl,
    float scale, int M, int N, int K, float* sm)
{
    const int tid  = threadIdx.x;
    const int lane = tid & 31;
    const int warp = tid >> 5;           // 0..3
    const int wm   = warp >> 1;          // 0..1 (32 rows)
    const int wn   = warp & 1;           // 0..1 (64 cols)

    const int mBase = blockIdx.y * GBM;
    const int nBase = blockIdx.x * GBN;

    const float* Ab = A  + (size_t)mBase * K;
    const float* Bb = Bt + (size_t)nBase * K;

    unsigned smem_base;
    asm("{ .reg .u64 t; cvta.to.shared.u64 t, %1; cvt.u32.u64 %0, t; }"
        : "=r"(smem_base) : "l"(sm));

    float c[2][8][4];
    #pragma unroll
    for (int mt = 0; mt < 2; mt++)
        #pragma unroll
        for (int nt = 0; nt < 8; nt++)
            #pragma unroll
            for (int e = 0; e < 4; e++) c[mt][nt][e] = 0.0f;

    const int niter = K / GBK;           // 32

    // cp.async: A 64 rows x 8 chunks = 512; B 128 rows x 8 chunks = 1024
    auto load_stage = [&](int iter, int buf) {
        const int k0 = iter * GBK;
        unsigned aBase = smem_base + (unsigned)(buf * STAGE_FLOATS) * 4u;
        unsigned bBase = aBase + GBM * TRS * 4u;
        #pragma unroll
        for (int it = 0; it < 4; it++) {
            int idx = tid + 128 * it;    // 0..511
            int r = idx >> 3, ch = idx & 7;
            cp_async16(aBase + (unsigned)(r * 144 + ch * 16),
                       Ab + (size_t)r * K + k0 + ch * 4);
        }
        #pragma unroll
        for (int it = 0; it < 8; it++) {
            int idx = tid + 128 * it;    // 0..1023
            int r = idx >> 3, ch = idx & 7;
            cp_async16(bBase + (unsigned)(r * 144 + ch * 16),
                       Bb + (size_t)r * K + k0 + ch * 4);
        }
    };

    load_stage(0, 0); cp_commit();
    load_stage(1, 1); cp_commit();

    // Precompute per-lane ldmatrix addresses (relative to region bases)
    unsigned aOff[2], bOff[4];
    {
        int arow_l = (lane & 7) + ((lane >> 3) & 1) * 8;   // row within 16
        int achk   = ((lane >> 4) & 1) * 16;               // 0 or 16 B
        #pragma unroll
        for (int mt = 0; mt < 2; mt++) {
            int row = wm * 32 + mt * 16 + arow_l;
            aOff[mt] = (unsigned)(row * 144 + achk);
        }
        int brow_l = (lane & 7) + ((lane >> 4) & 1) * 8;   // row within 16
        int bchk   = ((lane >> 3) & 1) * 16;               // 0 or 16 B
        #pragma unroll
        for (int p = 0; p < 4; p++) {
            int row = wn * 64 + p * 16 + brow_l;
            bOff[p] = (unsigned)(row * 144 + bchk);
        }
    }

    for (int i = 0; i < niter; i++) {
        cp_wait<1>();
        __syncthreads();

        const int buf = i & 1;
        unsigned aBase = smem_base + (unsigned)(buf * STAGE_FLOATS) * 4u;
        unsigned bBase = aBase + GBM * TRS * 4u;

        #pragma unroll
        for (int kk = 0; kk < GBK / 8; kk++) {
            unsigned koff = (unsigned)(kk * 32);   // 8 tf32 = 32 B
            unsigned af[2][4], bf[4][4];
            #pragma unroll
            for (int mt = 0; mt < 2; mt++) {
                ldsm_x4(af[mt], aBase + aOff[mt] + koff);
                #pragma unroll
                for (int e = 0; e < 4; e++)
                    af[mt][e] = f2tf32(__uint_as_float(af[mt][e]));
            }
            #pragma unroll
            for (int p = 0; p < 4; p++)
                ldsm_x4(bf[p], bBase + bOff[p] + koff);

            #pragma unroll
            for (int mt = 0; mt < 2; mt++)
                #pragma unroll
                for (int nt = 0; nt < 8; nt++)
                    mma_tf32(c[mt][nt], af[mt],
                             bf[nt >> 1][2 * (nt & 1)],
                             bf[nt >> 1][2 * (nt & 1) + 1]);
        }
        __syncthreads();
        if (i + 2 < niter) load_stage(i + 2, buf);
        cp_commit();
    }

    // Epilogue (same c-frag mapping as R8)
    const int g  = lane >> 2;
    const int tg = lane & 3;
    if (Ch) {
        #pragma unroll
        for (int mt = 0; mt < 2; mt++) {
            int r0 = mBase + wm * 32 + mt * 16 + g;
            #pragma unroll
            for (int nt = 0; nt < 8; nt++) {
                int col = nBase + wn * 64 + nt * 8 + 2 * tg;
                #pragma unroll
                for (int half = 0; half < 2; half++) {
                    size_t off = (size_t)(r0 + 8 * half) * N + col;
                    float y0 = c[mt][nt][2 * half + 0] * scale;
                    float y1 = c[mt][nt][2 * half + 1] * scale;
                    unsigned hi = packbf2(y1, y0);
                    float h0 = __uint_as_float(hi << 16);
                    float h1 = __uint_as_float(hi & 0xffff0000u);
                    unsigned lo = packbf2(y1 - h1, y0 - h0);
                    *(unsigned*)(Ch + off) = hi;
                    *(unsigned*)(Cl + off) = lo;
                }
            }
        }
    } else {
        #pragma unroll
        for (int mt = 0; mt < 2; mt++) {
            int r0 = mBase + wm * 32 + mt * 16 + g;
            #pragma unroll
            for (int nt = 0; nt < 8; nt++) {
                int col = nBase + wn * 64 + nt * 8 + 2 * tg;
                *(float2*)(Cf + (size_t)r0 * N + col) =
                    make_float2(c[mt][nt][0], c[mt][nt][1]);
                *(float2*)(Cf + (size_t)(r0 + 8) * N + col) =
                    make_float2(c[mt][nt][2], c[mt][nt][3]);
            }
        }
    }
}

// Fused Q/K/V projections: grid.z selects the GEMM.
__global__ void __launch_bounds__(128, 4)
qkv_gemm(const float* __restrict__ q, const float* __restrict__ k,
         const float* __restrict__ v, const float* __restrict__ Wt,
         __nv_bfloat16* Qh, __nv_bfloat16* Ql,
         __nv_bfloat16* Kh, __nv_bfloat16* Kl,
         __nv_bfloat16* Vh, __nv_bfloat16* Vl)
{
    extern __shared__ float sm[];
    const int z = blockIdx.z;
    const float* A = (z == 0) ? q  : (z == 1) ? k  : v;
    __nv_bfloat16* Ch = (z == 0) ? Qh : (z == 1) ? Kh : Vh;
    __nv_bfloat16* Cl = (z == 0) ? Ql : (z == 1) ? Kl : Vl;
    float scale = (z == 0) ? 0.125f : 1.0f;
    gemm_core(A, Wt + (size_t)z * WELEM, nullptr, Ch, Cl, scale,
              NTOK, DIM, DIM, sm);
}

__global__ void __launch_bounds__(128, 4)
wo_gemm(const float* __restrict__ A, const float* __restrict__ Wt,
        float* __restrict__ C)
{
    extern __shared__ float sm[];
    gemm_core(A, Wt + 3 * WELEM, C, nullptr, nullptr, 1.0f,
              NTOK, DIM, DIM, sm);
}

// ---------------------------------------------------------------------------
// Flash attention (exact R8 config — best measured): bf16 tensor cores,
// 3-term hi/lo split, 128-thread CTAs over 64 q-rows, 2 CTAs/SM,
// gmem-direct Q frags, 2-stage cp.async KV double-buffer, padded smem.
// ---------------------------------------------------------------------------
#define RS 72
#define KVSTAGE (4*64*RS)              // 18432 bf16 per stage
#define SB_TOTAL (2*KVSTAGE)           // 73728 B
#define OKH 0
#define OKL (64*RS)
#define OVH (128*RS)
#define OVL (192*RS)

__global__ void __launch_bounds__(128, 2)
flash_bf16(const __nv_bfloat16* __restrict__ Qh, const __nv_bfloat16* __restrict__ Ql,
           const __nv_bfloat16* __restrict__ Kh, const __nv_bfloat16* __restrict__ Kl,
           const __nv_bfloat16* __restrict__ Vh, const __nv_bfloat16* __restrict__ Vl,
           float* __restrict__ merged, float* __restrict__ attn_out,
           int write_attn, const int* __restrict__ maskedp)
{
    extern __shared__ __nv_bfloat16 sb[];
    const int qt  = gridDim.x - 1 - blockIdx.x;   // heavy blocks first
    const int h   = blockIdx.y;
    const int b   = blockIdx.z;
    const int tid = threadIdx.x;
    const int lane = tid & 31;
    const int w   = tid >> 5;                     // 0..3
    const int q0  = qt * 64;
    const int masked = maskedp[0];

    unsigned sbase;
    asm("{ .reg .u64 t; cvta.to.shared.u64 t, %1; cvt.u32.u64 %0, t; }"
        : "=r"(sbase) : "l"(sb));

    const int ktmax = masked ? qt : (SEQ / 64 - 1);

    auto stage_off = [](int kt) -> unsigned { return (kt & 1) ? (unsigned)KVSTAGE : 0u; };

    auto prefetch = [&](int t) {
        if (t <= ktmax) {
            unsigned so = stage_off(t);
            int r  = tid >> 3;
            int c8 = (tid & 7) << 3;
            #pragma unroll
            for (int quarter = 0; quarter < 4; quarter++) {
                int rr = r + 16 * quarter;
                size_t gidx = ((size_t)(b * SEQ + t * 64 + rr) * DIM) + h * HD + c8;
                unsigned sa = sbase + (so + rr * RS + c8) * 2;
                cp_async16(sa + OKH * 2, Kh + gidx);
                cp_async16(sa + OKL * 2, Kl + gidx);
                cp_async16(sa + OVH * 2, Vh + gidx);
                cp_async16(sa + OVL * 2, Vl + gidx);
            }
        }
        cp_commit();
    };

    prefetch(0);
    prefetch(1);

    unsigned qf[2][4][4];
    {
        const int g  = lane >> 2;
        const int tg = lane & 3;
        const int row0 = q0 + 16 * w + g;
        size_t base0 = ((size_t)(b * SEQ + row0)     * DIM) + h * HD;
        size_t base1 = ((size_t)(b * SEQ + row0 + 8) * DIM) + h * HD;
        #pragma unroll
        for (int d = 0; d < 4; d++) {
            int c0 = 16 * d + 2 * tg;
            qf[0][d][0] = *(const unsigned*)(Qh + base0 + c0);
            qf[0][d][1] = *(const unsigned*)(Qh + base1 + c0);
            qf[0][d][2] = *(const unsigned*)(Qh + base0 + c0 + 8);
            qf[0][d][3] = *(const unsigned*)(Qh + base1 + c0 + 8);
            qf[1][d][0] = *(const unsigned*)(Ql + base0 + c0);
            qf[1][d][1] = *(const unsigned*)(Ql + base1 + c0);
            qf[1][d][2] = *(const unsigned*)(Ql + base0 + c0 + 8);
            qf[1][d][3] = *(const unsigned*)(Ql + base1 + c0 + 8);
        }
    }

    float o[8][4];
    #pragma unroll
    for (int j = 0; j < 8; j++)
        #pragma unroll
        for (int e = 0; e < 4; e++) o[j][e] = 0.0f;
    float m0 = -1e30f, m1 = -1e30f, l0 = 0.0f, l1 = 0.0f;

    const int r_lo = q0 + 16 * w + (lane >> 2);
    const int r_hi = r_lo + 8;

    for (int kt = 0; kt <= ktmax; kt++) {
        cp_wait<1>();
        __syncthreads();

        const unsigned so = stage_off(kt);
        const int k0 = kt * 64;

        float s[8][4];
        #pragma unroll
        for (int j = 0; j < 8; j++)
            #pragma unroll
            for (int e = 0; e < 4; e++) s[j][e] = 0.0f;

        #pragma unroll
        for (int j = 0; j < 8; j++) {
            unsigned kbh[8], kbl[8];
            int krow = 8 * j + (lane & 7);
            int dct  = (lane >> 3) << 3;
            ldsm_x4(&kbh[0], sbase + (so + OKH + krow * RS + dct) * 2);
            ldsm_x4(&kbh[4], sbase + (so + OKH + krow * RS + 32 + dct) * 2);
            ldsm_x4(&kbl[0], sbase + (so + OKL + krow * RS + dct) * 2);
            ldsm_x4(&kbl[4], sbase + (so + OKL + krow * RS + 32 + dct) * 2);
            #pragma unroll
            for (int d = 0; d < 4; d++) {
                mma_bf16(s[j], qf[0][d], kbh[2*d], kbh[2*d+1]);
                mma_bf16(s[j], qf[0][d], kbl[2*d], kbl[2*d+1]);
                mma_bf16(s[j], qf[1][d], kbh[2*d], kbh[2*d+1]);
            }
        }

        if (masked && kt == qt) {
            #pragma unroll
            for (int j = 0; j < 8; j++) {
                int cc = k0 + 8 * j + 2 * (lane & 3);
                if (cc     > r_lo) s[j][0] = -1e30f;
                if (cc + 1 > r_lo) s[j][1] = -1e30f;
                if (cc     > r_hi) s[j][2] = -1e30f;
                if (cc + 1 > r_hi) s[j][3] = -1e30f;
            }
        }

        float mt0 = -1e30f, mt1 = -1e30f;
        #pragma unroll
        for (int j = 0; j < 8; j++) {
            mt0 = fmaxf(mt0, fmaxf(s[j][0], s[j][1]));
            mt1 = fmaxf(mt1, fmaxf(s[j][2], s[j][3]));
        }
        mt0 = fmaxf(mt0, __shfl_xor_sync(0xffffffffu, mt0, 1));
        mt0 = fmaxf(mt0, __shfl_xor_sync(0xffffffffu, mt0, 2));
        mt1 = fmaxf(mt1, __shfl_xor_sync(0xffffffffu, mt1, 1));
        mt1 = fmaxf(mt1, __shfl_xor_sync(0xffffffffu, mt1, 2));
        float mn0 = fmaxf(m0, mt0), mn1 = fmaxf(m1, mt1);
        float a0 = __expf(m0 - mn0), a1 = __expf(m1 - mn1);
        m0 = mn0; m1 = mn1;

        float rs0 = 0.0f, rs1 = 0.0f;
        unsigned pah[4][4], pal[4][4];
        #pragma unroll
        for (int j = 0; j < 8; j++) {
            float p0 = __expf(s[j][0] - mn0);
            float p1 = __expf(s[j][1] - mn0);
            float p2 = __expf(s[j][2] - mn1);
            float p3 = __expf(s[j][3] - mn1);
            rs0 += p0 + p1; rs1 += p2 + p3;
            unsigned h01 = packbf2(p1, p0);
            unsigned h23 = packbf2(p3, p2);
            float q0f = __uint_as_float(h01 << 16);
            float q1f = __uint_as_float(h01 & 0xffff0000u);
            float q2f = __uint_as_float(h23 << 16);
            float q3f = __uint_as_float(h23 & 0xffff0000u);
            unsigned lo01 = packbf2(p1 - q1f, p0 - q0f);
            unsigned lo23 = packbf2(p3 - q3f, p2 - q2f);
            int t = j >> 1, half = j & 1;
            pah[t][2 * half + 0] = h01;
            pah[t][2 * half + 1] = h23;
            pal[t][2 * half + 0] = lo01;
            pal[t][2 * half + 1] = lo23;
        }
        rs0 += __shfl_xor_sync(0xffffffffu, rs0, 1);
        rs0 += __shfl_xor_sync(0xffffffffu, rs0, 2);
        rs1 += __shfl_xor_sync(0xffffffffu, rs1, 1);
        rs1 += __shfl_xor_sync(0xffffffffu, rs1, 2);
        l0 = l0 * a0 + rs0;
        l1 = l1 * a1 + rs1;
        #pragma unroll
        for (int j = 0; j < 8; j++) {
            o[j][0] *= a0; o[j][1] *= a0;
            o[j][2] *= a1; o[j][3] *= a1;
        }

        #pragma unroll
        for (int jn = 0; jn < 8; jn++) {
            unsigned vbh[8], vbl[8];
            ldsm_x4_t(&vbh[0], sbase + (so + OVH + lane * RS + 8 * jn) * 2);
            ldsm_x4_t(&vbh[4], sbase + (so + OVH + (32 + lane) * RS + 8 * jn) * 2);
            ldsm_x4_t(&vbl[0], sbase + (so + OVL + lane * RS + 8 * jn) * 2);
            ldsm_x4_t(&vbl[4], sbase + (so + OVL + (32 + lane) * RS + 8 * jn) * 2);
            #pragma unroll
            for (int t = 0; t < 4; t++) {
                mma_bf16(o[jn], pah[t], vbh[2*t], vbh[2*t+1]);
                mma_bf16(o[jn], pah[t], vbl[2*t], vbl[2*t+1]);
                mma_bf16(o[jn], pal[t], vbh[2*t], vbh[2*t+1]);
            }
        }

        __syncthreads();
        prefetch(kt + 2);
    }

    float il0 = 1.0f / l0, il1 = 1.0f / l1;
    #pragma unroll
    for (int jn = 0; jn < 8; jn++) {
        int col = 8 * jn + 2 * (lane & 3);
        float f00 = o[jn][0] * il0, f01 = o[jn][1] * il0;
        float f10 = o[jn][2] * il1, f11 = o[jn][3] * il1;
        *(float2*)(merged + ((size_t)(b * SEQ + r_lo) * DIM) + h * HD + col) =
            make_float2(f00, f01);
        *(float2*)(merged + ((size_t)(b * SEQ + r_hi) * DIM) + h * HD + col) =
            make_float2(f10, f11);
        if (write_attn) {
            *(float2*)(attn_out + (((size_t)(b * NH + h) * SEQ + r_lo) * HD) + col) =
                make_float2(f00, f01);
            *(float2*)(attn_out + (((size_t)(b * NH + h) * SEQ + r_hi) * HD) + col) =
                make_float2(f10, f11);
        }
    }
}

// ---------------------------------------------------------------------------
extern "C" void kernel_launch(void* const* d_in, const int* in_sizes, int n_in,
                              void* d_out, int out_size)
{
    const float* q  = (const float*)d_in[0];
    const float* k  = (const float*)d_in[1];
    const float* v  = (const float*)d_in[2];
    const float* Wq = (const float*)d_in[3];
    const float* Wk = (const float*)d_in[4];
    const float* Wv = (const float*)d_in[5];
    const float* Wo = (const float*)d_in[6];
    const int* masked = (const int*)d_in[7];
    float* out = (float*)d_out;

    float *pM, *pWt;
    __nv_bfloat16 *pQh, *pQl, *pKh, *pKl, *pVh, *pVl;
    cudaGetSymbolAddress((void**)&pM,  g_M);
    cudaGetSymbolAddress((void**)&pWt, g_Wt);
    cudaGetSymbolAddress((void**)&pQh, g_Qh);
    cudaGetSymbolAddress((void**)&pQl, g_Ql);
    cudaGetSymbolAddress((void**)&pKh, g_Kh);
    cudaGetSymbolAddress((void**)&pKl, g_Kl);
    cudaGetSymbolAddress((void**)&pVh, g_Vh);
    cudaGetSymbolAddress((void**)&pVl, g_Vl);

    cudaFuncSetAttribute(qkv_gemm, cudaFuncAttributeMaxDynamicSharedMemorySize,
                         GEMM_SMEM);
    cudaFuncSetAttribute(wo_gemm, cudaFuncAttributeMaxDynamicSharedMemorySize,
                         GEMM_SMEM);

    // Pre-pass: transpose + RNA-round all 4 weight matrices
    dim3 gTr(DIM / 32, DIM / 32, 4);
    wtrans<<<gTr, dim3(32, 32)>>>(Wq, Wk, Wv, Wo, pWt);

    // Fused Q/K/V projections (ldmatrix tf32 core)
    dim3 gQKV(DIM / GBN, NTOK / GBM, 3);   // (8, 64, 3)
    qkv_gemm<<<gQKV, 128, GEMM_SMEM>>>(q, k, v, pWt,
                                       pQh, pQl, pKh, pKl, pVh, pVl);

    // Attention (exact R8 config)
    int write_attn = (out_size >= (int)(2 * NELEM)) ? 1 : 0;
    float* attn_ptr = out + NELEM;
    size_t fl_smem = (size_t)SB_TOTAL * sizeof(__nv_bfloat16);
    cudaFuncSetAttribute(flash_bf16, cudaFuncAttributeMaxDynamicSharedMemorySize,
                         (int)fl_smem);
    dim3 gAttn(SEQ / 64, NH, BSZ);         // (32, 16, 2)
    flash_bf16<<<gAttn, 128, fl_smem>>>(pQh, pQl, pKh, pKl, pVh, pVl,
                                        pM, attn_ptr, write_attn, masked);

    // Output projection (ldmatrix tf32 core)
    dim3 gWo(DIM / GBN, NTOK / GBM);       // (8, 64)
    wo_gemm<<<gWo, 128, GEMM_SMEM>>>(pM, pWt, out);
}